// round 9
// baseline (speedup 1.0000x reference)
#include <cuda_runtime.h>
#include <cuda_bf16.h>
#include <cstdint>

// B=16, K=32, H=W=28, HID=OUT=64, NOPS=8, N = B*K = 512 images
#define NIMG 512
#define FC_SPLIT 49
#define FC_SLICE 64      // 3136 / 49

typedef unsigned long long ull;

// ---------------- packed fp32x2 helpers ----------------------------------------
__device__ __forceinline__ ull pk2(float lo, float hi) {
    ull d;
    asm("mov.b64 %0, {%1, %2};" : "=l"(d)
        : "r"(__float_as_uint(lo)), "r"(__float_as_uint(hi)));
    return d;
}
__device__ __forceinline__ float2 upk2(ull v) {
    unsigned int lo, hi;
    asm("mov.b64 {%0, %1}, %2;" : "=r"(lo), "=r"(hi) : "l"(v));
    float2 f; f.x = __uint_as_float(lo); f.y = __uint_as_float(hi);
    return f;
}
__device__ __forceinline__ ull f2fma(ull a, ull b, ull c) {
    ull d;
    asm("fma.rn.f32x2 %0, %1, %2, %3;" : "=l"(d) : "l"(a), "l"(b), "l"(c));
    return d;
}
__device__ __forceinline__ ull f2mul(ull a, ull b) {
    ull d;
    asm("mul.rn.f32x2 %0, %1, %2;" : "=l"(d) : "l"(a), "l"(b));
    return d;
}

// ---------------- scratch -----------------------------------------------------
__device__ float g_h1p[NIMG * 32 * 14 * 14];     // conv1 out, PIXEL-major [n][pix][ci]
__device__ float g_h2p[NIMG * 64 * 7 * 7];       // conv2 out [n][co][pix]
__device__ float g_feat[NIMG * 64];              // fc+relu out
__device__ float g_wt[8 * 64 * 64];              // eq_w transposed: [o][d*64+e]
__device__ float g_part[NIMG * 64];              // per-(b,k) partial relu-sums
__device__ float g_fcpart[FC_SPLIT * NIMG * 64]; // fc k-split partials
__device__ ull   g_w2[16 * 9 * 64];              // conv2 w, [cipair][k][co] = {w_ci, w_ci+1}

// ---------------- kernel 0: transpose eq_w + pack conv2 weights ----------------
__global__ void k_prep(const float* __restrict__ eq_w,
                       const float* __restrict__ conv2_w) {
    int gid = blockIdx.x * blockDim.x + threadIdx.x;
    int nth = gridDim.x * blockDim.x;
    for (int idx = gid; idx < 8 * 64 * 64; idx += nth) {
        int o = idx & 7;
        int de = idx >> 3;                       // d*64 + e
        g_wt[o * 4096 + de] = eq_w[idx];
    }
    // g_w2[(cp*9 + k)*64 + co] = {w[co][2cp][k], w[co][2cp+1][k]}
    for (int idx = gid; idx < 9216; idx += nth) {
        int co = idx & 63;
        int k = (idx >> 6) % 9;
        int cp = idx / 576;
        g_w2[idx] = pk2(conv2_w[co * 288 + (2 * cp) * 9 + k],
                        conv2_w[co * 288 + (2 * cp + 1) * 9 + k]);
    }
}

// ---------------- kernel 1: conv1(1->32) + relu + maxpool2, pixel-major out ----
__global__ void __launch_bounds__(224) k_conv1(const float* __restrict__ x,
                                               const float* __restrict__ w,
                                               const float* __restrict__ bias) {
    __shared__ float smin[784];
    __shared__ float smw[288];
    __shared__ float smb[32];
    __shared__ float sout[196 * 33];
    int n = blockIdx.x;
    int tid = threadIdx.x;
    for (int idx = tid; idx < 784; idx += 224) smin[idx] = x[n * 784 + idx];
    for (int idx = tid; idx < 288; idx += 224) smw[idx] = w[idx];
    if (tid < 32) smb[tid] = bias[tid];
    __syncthreads();

    if (tid < 196) {
        int oy = tid / 14, ox = tid % 14;
        float patch[4][4];
#pragma unroll
        for (int r = 0; r < 4; r++) {
            int y = oy * 2 - 1 + r;
#pragma unroll
            for (int cc = 0; cc < 4; cc++) {
                int xx = ox * 2 - 1 + cc;
                patch[r][cc] = (y >= 0 && y < 28 && xx >= 0 && xx < 28)
                                   ? smin[y * 28 + xx] : 0.f;
            }
        }
        ull pp[4][3];
#pragma unroll
        for (int r = 0; r < 4; r++)
#pragma unroll
            for (int kx = 0; kx < 3; kx++)
                pp[r][kx] = pk2(patch[r][kx], patch[r][kx + 1]);

#pragma unroll 4
        for (int co = 0; co < 32; co++) {
            float b0 = smb[co];
            ull accT = pk2(b0, b0);
            ull accB = pk2(b0, b0);
            const float* wp = smw + co * 9;
#pragma unroll
            for (int ky = 0; ky < 3; ky++)
#pragma unroll
                for (int kx = 0; kx < 3; kx++) {
                    float wv = wp[ky * 3 + kx];
                    ull w2 = pk2(wv, wv);
                    accT = f2fma(pp[ky][kx],     w2, accT);
                    accB = f2fma(pp[ky + 1][kx], w2, accB);
                }
            float2 t = upk2(accT), bt = upk2(accB);
            float m = fmaxf(fmaxf(t.x, t.y), fmaxf(bt.x, bt.y));
            sout[tid * 33 + co] = fmaxf(m, 0.f);
        }
    }
    __syncthreads();
    // coalesced pixel-major write: g_h1p[n][pix][ci]
    for (int idx = tid; idx < 6272; idx += 224) {
        int pix = idx >> 5, ci = idx & 31;
        g_h1p[n * 6272 + idx] = sout[pix * 33 + ci];
    }
}

// ---------------- kernel 2: conv2(32->64) + relu + maxpool2 --------------------
// pixel-major image with zero halo (16x16, stride 34), ci-pair packed f32x2.
// 392 thr = 8 co-groups x 49 pooled pixels, 8 co per thread.
// dyn smem: weights 73728 B | image 8704 floats (34816 B) = 108544 B.
__global__ void __launch_bounds__(392) k_conv2(const float* __restrict__ bias) {
    extern __shared__ char smraw[];
    ull*   smw2  = (ull*)smraw;                   // 9216 ull
    float* smimg = (float*)(smraw + 73728);       // 8704 floats
    int n = blockIdx.x;
    int tid = threadIdx.x;
    for (int idx = tid; idx < 9216; idx += 392) smw2[idx] = g_w2[idx];
    for (int idx = tid; idx < 8704; idx += 392) smimg[idx] = 0.f;
    __syncthreads();
    for (int idx = tid; idx < 6272; idx += 392) {
        int pix = idx >> 5, ci = idx & 31;
        int y = pix / 14, xx = pix - y * 14;
        smimg[((y + 1) * 16 + (xx + 1)) * 34 + ci] = g_h1p[n * 6272 + idx];
    }
    __syncthreads();

    int cog = tid / 49;
    int pslot = tid - cog * 49;
    int oy = pslot / 7, ox = pslot % 7;
    int c0 = cog * 8;
    int sbase = (oy * 2) * 16 + (ox * 2);

    ull acc[8][4];
#pragma unroll
    for (int co = 0; co < 8; co++) {
        ull bp = pk2(__ldg(&bias[c0 + co]), 0.f);   // bias once, in .x half
        acc[co][0] = bp; acc[co][1] = bp; acc[co][2] = bp; acc[co][3] = bp;
    }

    for (int cp = 0; cp < 16; cp++) {
        const float* ip = smimg + 2 * cp;
        ull pd[4][4];
#pragma unroll
        for (int r = 0; r < 4; r++)
#pragma unroll
            for (int cc = 0; cc < 4; cc++)
                pd[r][cc] = *(const ull*)(ip + (sbase + r * 16 + cc) * 34);

        const ull* wb = smw2 + cp * 576 + c0;       // [cp][k][co]
#pragma unroll
        for (int ky = 0; ky < 3; ky++)
#pragma unroll
            for (int kx = 0; kx < 3; kx++) {
                const ull* wk_ = wb + (ky * 3 + kx) * 64;
#pragma unroll
                for (int co = 0; co < 8; co++) {
                    ull wv = wk_[co];
                    acc[co][0] = f2fma(pd[ky][kx],         wv, acc[co][0]);
                    acc[co][1] = f2fma(pd[ky][kx + 1],     wv, acc[co][1]);
                    acc[co][2] = f2fma(pd[ky + 1][kx],     wv, acc[co][2]);
                    acc[co][3] = f2fma(pd[ky + 1][kx + 1], wv, acc[co][3]);
                }
            }
    }
#pragma unroll
    for (int co = 0; co < 8; co++) {
        float2 v0 = upk2(acc[co][0]);
        float2 v1 = upk2(acc[co][1]);
        float2 v2 = upk2(acc[co][2]);
        float2 v3 = upk2(acc[co][3]);
        float s0 = v0.x + v0.y, s1 = v1.x + v1.y;
        float s2 = v2.x + v2.y, s3 = v3.x + v3.y;
        float m = fmaxf(fmaxf(s0, s1), fmaxf(s2, s3));
        g_h2p[n * 3136 + (c0 + co) * 49 + pslot] = fmaxf(m, 0.f);
    }
}

// ---------------- kernel 3: fc GEMM -------------------------------------------
__global__ void __launch_bounds__(256) k_fc(const float* __restrict__ fcw) {
    __shared__ float As[16][68];
    __shared__ float Bs[16][68];
    int mt = blockIdx.x / FC_SPLIT, ks = blockIdx.x - mt * FC_SPLIT;
    int n0 = mt * 64, kbase = ks * FC_SLICE;
    int tid = threadIdx.x;
    int ty = tid >> 4, tx = tid & 15;
    int lrow = tid >> 2;
    int lkq  = tid & 3;

    float acc[4][4] = {};
    for (int kb = 0; kb < FC_SLICE; kb += 16) {
        float4 a4 = *(const float4*)&g_h2p[(n0 + lrow) * 3136 + kbase + kb + lkq * 4];
        float4 b4 = *(const float4*)&fcw[lrow * 3136 + kbase + kb + lkq * 4];
        __syncthreads();
        As[lkq * 4 + 0][lrow] = a4.x; As[lkq * 4 + 1][lrow] = a4.y;
        As[lkq * 4 + 2][lrow] = a4.z; As[lkq * 4 + 3][lrow] = a4.w;
        Bs[lkq * 4 + 0][lrow] = b4.x; Bs[lkq * 4 + 1][lrow] = b4.y;
        Bs[lkq * 4 + 2][lrow] = b4.z; Bs[lkq * 4 + 3][lrow] = b4.w;
        __syncthreads();
#pragma unroll
        for (int kk = 0; kk < 16; kk++) {
            float4 av = *(const float4*)&As[kk][ty * 4];
            float4 bv = *(const float4*)&Bs[kk][tx * 4];
            float a[4] = {av.x, av.y, av.z, av.w};
            float bb[4] = {bv.x, bv.y, bv.z, bv.w};
#pragma unroll
            for (int m = 0; m < 4; m++)
#pragma unroll
                for (int nn = 0; nn < 4; nn++)
                    acc[m][nn] = fmaf(a[m], bb[nn], acc[m][nn]);
        }
    }
    float* outp = g_fcpart + ks * (NIMG * 64);
#pragma unroll
    for (int m = 0; m < 4; m++)
#pragma unroll
        for (int nn = 0; nn < 4; nn++)
            outp[(n0 + ty * 4 + m) * 64 + tx * 4 + nn] = acc[m][nn];
}

__global__ void __launch_bounds__(512) k_fcred(const float* __restrict__ fcb) {
    int idx = blockIdx.x * 512 + threadIdx.x;
    float s = 0.f;
#pragma unroll
    for (int r = 0; r < FC_SPLIT; r++) s += g_fcpart[r * (NIMG * 64) + idx];
    g_feat[idx] = fmaxf(s + fcb[idx & 63], 0.f);
}

// ---------------- kernel 4: equivariant block (i-pair accs, duplicated WK) -----
// smem floats: At[0,2304) | WKD/T [2304,10496) | ROWf [10496,12544)
//              | COLt [12544,14592) | S [14592) | R [14656) ; total 14720 = 58880B
__global__ void __launch_bounds__(256, 2) k_eq(const float* __restrict__ eq_b) {
    extern __shared__ float sm[];
    float* At   = sm;
    float* T    = sm + 2304;            // temp (first 4096 of WKD region)
    ull*   WKD  = (ull*)(sm + 2304);    // 4096 ull = 8192 floats
    float* ROWf = sm + 10496;           // [ig][e*8 + il]  (il = i&7)
    float* COLt = sm + 12544;           // [e*32 + j]
    float* S    = sm + 14592;
    float* R    = sm + 14656;

    int b = blockIdx.x >> 5;
    int k = blockIdx.x & 31;
    int tid = threadIdx.x, warp = tid >> 5, lane = tid & 31;

    const float* W0 = g_wt;
    const float* W1 = g_wt + 1 * 4096;
    const float* W2 = g_wt + 2 * 4096;
    const float* W3 = g_wt + 3 * 4096;
    const float* W4 = g_wt + 4 * 4096;
    const float* W5 = g_wt + 5 * 4096;
    const float* W6 = g_wt + 6 * 4096;
    const float* W7 = g_wt + 7 * 4096;

    for (int idx = tid; idx < 2048; idx += 256) {
        int i = idx >> 6, d = idx & 63;
        At[d * 36 + i] = g_feat[b * 2048 + idx];
    }
    __syncthreads();
    if (tid < 64) {
        float a = 0.f;
#pragma unroll
        for (int i = 0; i < 32; i++) a += At[tid * 36 + i];
        S[tid] = a * (1.f / 32.f);
    }
    __syncthreads();

    // T = row temp
    for (int idx = tid; idx < 4096; idx += 256) {
        int d = idx >> 6;
        float sd = S[d];
        T[idx] = sd * fmaf(At[d * 36 + k], W2[idx], sd * W6[idx]);
    }
    if (tid < 64) {
        float acc = 0.f;
        for (int d = 0; d < 64; d++) {
            float sd = S[d];
            acc += sd * sd * fmaf(At[d * 36 + k], W4[d * 64 + tid], sd * W7[d * 64 + tid]);
        }
        R[tid] = acc + eq_b[tid];
    }
    __syncthreads();

    // ROW build -> interleaved layout ROWf[(i>>3)*512 + e*8 + (i&7)]
    for (int idx = tid; idx < 1024; idx += 256) {
        int i = idx >> 5, ep = (idx & 31) * 2;
        ull acc = pk2(0.f, 0.f);
#pragma unroll 8
        for (int d = 0; d < 64; d++) {
            float a = At[d * 36 + i];
            acc = f2fma(pk2(a, a), *(const ull*)(T + d * 64 + ep), acc);
        }
        float2 r = upk2(acc);
        int base = (i >> 3) * 512 + (i & 7);
        ROWf[base + ep * 8]       = r.x;
        ROWf[base + (ep + 1) * 8] = r.y;
    }
    __syncthreads();

    // T = col temp
    for (int idx = tid; idx < 4096; idx += 256) {
        int d = idx >> 6;
        float sd = S[d];
        T[idx] = sd * fmaf(At[d * 36 + k], W1[idx], sd * W5[idx]);
    }
    __syncthreads();

    // COLt[e*32+j]
    for (int idx = tid; idx < 1024; idx += 256) {
        int ep = (idx >> 5) * 2, j = idx & 31;
        ull acc = pk2(0.f, 0.f);
#pragma unroll 8
        for (int d = 0; d < 64; d++) {
            float a = At[d * 36 + j];
            acc = f2fma(pk2(a, a), *(const ull*)(T + d * 64 + ep), acc);
        }
        float2 r = upk2(acc);
        COLt[ep * 32 + j] = r.x;
        COLt[(ep + 1) * 32 + j] = r.y;
    }
    __syncthreads();

    // WKD[d*64+e] = {wk, wk} duplicated  (overwrites T)
    for (int idx = tid; idx < 4096; idx += 256) {
        int d = idx >> 6;
        float wk = fmaf(At[d * 36 + k], W0[idx], S[d] * W3[idx]);
        WKD[idx] = pk2(wk, wk);
    }
    __syncthreads();

    int e0 = warp * 8;
    float esum[8] = {0, 0, 0, 0, 0, 0, 0, 0};
    ull cbd[8];
    const ull ONE2 = pk2(1.f, 1.f);
#pragma unroll
    for (int t = 0; t < 8; t++) {
        float cb = COLt[(e0 + t) * 32 + lane] + R[e0 + t];
        cbd[t] = pk2(cb, cb);
    }

    for (int ig = 0; ig < 4; ig++) {
        ull acc[4][8];
        const ull* rp4 = (const ull*)(ROWf + ig * 512) + e0 / 2 * 4;  // ull idx e*4+rp, e rel e0? no:
        // ROWf ull view: index = e*4 + rp ; our e starts at e0
        const ull* rbase = (const ull*)(ROWf + ig * 512);
#pragma unroll
        for (int t = 0; t < 8; t++) {
            const ull* re = rbase + (e0 + t) * 4;
            acc[0][t] = f2fma(re[0], ONE2, cbd[t]);
            acc[1][t] = f2fma(re[1], ONE2, cbd[t]);
            acc[2][t] = f2fma(re[2], ONE2, cbd[t]);
            acc[3][t] = f2fma(re[3], ONE2, cbd[t]);
        }
        (void)rp4;

#pragma unroll 4
        for (int d = 0; d < 64; d++) {
            float aj = At[d * 36 + lane];
            ull aj2 = pk2(aj, aj);
            const float* ai = At + d * 36 + ig * 8;
            ull c0 = f2mul(*(const ull*)(ai + 0), aj2);
            ull c1 = f2mul(*(const ull*)(ai + 2), aj2);
            ull c2 = f2mul(*(const ull*)(ai + 4), aj2);
            ull c3 = f2mul(*(const ull*)(ai + 6), aj2);
            const ull* wd = WKD + d * 64 + e0;
            ull w0 = wd[0], w1 = wd[1], w2 = wd[2], w3 = wd[3];
            ull w4 = wd[4], w5 = wd[5], w6 = wd[6], w7 = wd[7];
            acc[0][0] = f2fma(c0, w0, acc[0][0]);
            acc[0][1] = f2fma(c0, w1, acc[0][1]);
            acc[0][2] = f2fma(c0, w2, acc[0][2]);
            acc[0][3] = f2fma(c0, w3, acc[0][3]);
            acc[0][4] = f2fma(c0, w4, acc[0][4]);
            acc[0][5] = f2fma(c0, w5, acc[0][5]);
            acc[0][6] = f2fma(c0, w6, acc[0][6]);
            acc[0][7] = f2fma(c0, w7, acc[0][7]);
            acc[1][0] = f2fma(c1, w0, acc[1][0]);
            acc[1][1] = f2fma(c1, w1, acc[1][1]);
            acc[1][2] = f2fma(c1, w2, acc[1][2]);
            acc[1][3] = f2fma(c1, w3, acc[1][3]);
            acc[1][4] = f2fma(c1, w4, acc[1][4]);
            acc[1][5] = f2fma(c1, w5, acc[1][5]);
            acc[1][6] = f2fma(c1, w6, acc[1][6]);
            acc[1][7] = f2fma(c1, w7, acc[1][7]);
            acc[2][0] = f2fma(c2, w0, acc[2][0]);
            acc[2][1] = f2fma(c2, w1, acc[2][1]);
            acc[2][2] = f2fma(c2, w2, acc[2][2]);
            acc[2][3] = f2fma(c2, w3, acc[2][3]);
            acc[2][4] = f2fma(c2, w4, acc[2][4]);
            acc[2][5] = f2fma(c2, w5, acc[2][5]);
            acc[2][6] = f2fma(c2, w6, acc[2][6]);
            acc[2][7] = f2fma(c2, w7, acc[2][7]);
            acc[3][0] = f2fma(c3, w0, acc[3][0]);
            acc[3][1] = f2fma(c3, w1, acc[3][1]);
            acc[3][2] = f2fma(c3, w2, acc[3][2]);
            acc[3][3] = f2fma(c3, w3, acc[3][3]);
            acc[3][4] = f2fma(c3, w4, acc[3][4]);
            acc[3][5] = f2fma(c3, w5, acc[3][5]);
            acc[3][6] = f2fma(c3, w6, acc[3][6]);
            acc[3][7] = f2fma(c3, w7, acc[3][7]);
        }

#pragma unroll
        for (int rp = 0; rp < 4; rp++)
#pragma unroll
            for (int t = 0; t < 8; t++) {
                float2 v = upk2(acc[rp][t]);
                esum[t] += fmaxf(v.x, 0.f) + fmaxf(v.y, 0.f);
            }
    }

#pragma unroll
    for (int t = 0; t < 8; t++) {
        float v = esum[t];
#pragma unroll
        for (int off = 16; off; off >>= 1)
            v += __shfl_down_sync(0xffffffffu, v, off);
        if (lane == 0) g_part[blockIdx.x * 64 + e0 + t] = v;
    }
}

// ---------------- kernel 5: reduce over k, relu, final linear -----------------
__global__ void __launch_bounds__(512) k_out(const float* __restrict__ out_w,
                                             const float* __restrict__ out_b,
                                             float* __restrict__ out) {
    int tid = threadIdx.x;
    int bb = tid >> 5;
    int lane = tid & 31;
    float a0 = 0.f, a1 = 0.f;
    for (int k = 0; k < 32; k++) {
        const float* p = g_part + (bb * 32 + k) * 64;
        a0 += p[lane];
        a1 += p[lane + 32];
    }
    float x0 = fmaxf(a0 * (1.f / 32768.f), 0.f);
    float x1 = fmaxf(a1 * (1.f / 32768.f), 0.f);
    float acc = x0 * out_w[lane] + x1 * out_w[lane + 32];
#pragma unroll
    for (int off = 16; off; off >>= 1)
        acc += __shfl_down_sync(0xffffffffu, acc, off);
    if (lane == 0) out[bb] = acc + out_b[0];
}

// ---------------- launch ------------------------------------------------------
extern "C" void kernel_launch(void* const* d_in, const int* in_sizes, int n_in,
                              void* d_out, int out_size) {
    const float* x       = (const float*)d_in[0];
    const float* conv1_w = (const float*)d_in[1];
    const float* conv1_b = (const float*)d_in[2];
    const float* conv2_w = (const float*)d_in[3];
    const float* conv2_b = (const float*)d_in[4];
    const float* fc_w    = (const float*)d_in[5];
    const float* fc_b    = (const float*)d_in[6];
    const float* eq_w    = (const float*)d_in[7];
    const float* eq_b    = (const float*)d_in[8];
    const float* out_w   = (const float*)d_in[9];
    const float* out_b   = (const float*)d_in[10];
    float* out = (float*)d_out;

    cudaFuncSetAttribute(k_conv2, cudaFuncAttributeMaxDynamicSharedMemorySize, 108544);
    cudaFuncSetAttribute(k_eq,    cudaFuncAttributeMaxDynamicSharedMemorySize, 58880);

    k_prep<<<16, 256>>>(eq_w, conv2_w);
    k_conv1<<<NIMG, 224>>>(x, conv1_w, conv1_b);
    k_conv2<<<NIMG, 392, 108544>>>(conv2_b);
    k_fc<<<8 * FC_SPLIT, 256>>>(fc_w);
    k_fcred<<<64, 512>>>(fc_b);
    k_eq<<<NIMG, 256, 58880>>>(eq_b);
    k_out<<<1, 512>>>(out_w, out_b, out);
}